// round 10
// baseline (speedup 1.0000x reference)
#include <cuda_runtime.h>
#include <cuda_fp16.h>
#include <cuda_bf16.h>

// LightGCN: CSR SpMM x3, fp16 feature buffers, fp32 row accumulation.
// Round 10 (resubmit of R9 after infra failure): atomic-free scatter. The
// histogram's atomicAdd return value IS the edge's within-row rank; store
// it during hist, then scatter computes pos = rowptr[src] + rank[e] with
// no atomics and 4 independent edges per thread. Degree-perm dropped
// (measured neutral in R8).

constexpr int NUSERS = 100000;
constexpr int NITEMS = 50000;
constexpr int NNODES = 150000;
constexpr int NNZ_E  = 4800000;
constexpr int HVEC   = NNODES * 8;    // uint4 (8 halves) per fp16 buffer

constexpr int TB           = 256;
constexpr int SCAN_NBLK    = (NNODES + TB - 1) / TB;        // 586
constexpr int EDGE4_BLOCKS = (NNZ_E / 4 + TB - 1) / TB;     // 4688
constexpr int HVEC_BLOCKS  = (HVEC + TB - 1) / TB;          // 4688

// ---- scratch ----
struct ZeroRegion {                    // zeroed with ONE cudaMemsetAsync
    int cnt[NNODES];
    unsigned long long state[SCAN_NBLK];
    unsigned int ticket;
};
__device__ ZeroRegion g_zs;
__device__ uint4 g_h0[HVEC];
__device__ uint4 g_h1[HVEC];
__device__ uint4 g_h2[HVEC];
__device__ int   g_rowptr[NNODES + 1];
__device__ int   g_rank[NNZ_E];        // within-row rank of each edge
__device__ int2  g_meta[NNZ_E];        // {dst, val bits} grouped by src

// ---------------- CSR build ----------------

// Histogram; the atomic return value is the edge's rank within its row.
__global__ void hist_kernel(const int4* __restrict__ src4) {
    int t = blockIdx.x * blockDim.x + threadIdx.x;
    if (t < NNZ_E / 4) {
        int4 s = __ldg(&src4[t]);
        int r0 = atomicAdd(&g_zs.cnt[s.x], 1);
        int r1 = atomicAdd(&g_zs.cnt[s.y], 1);
        int r2 = atomicAdd(&g_zs.cnt[s.z], 1);
        int r3 = atomicAdd(&g_zs.cnt[s.w], 1);
        reinterpret_cast<int4*>(g_rank)[t] = make_int4(r0, r1, r2, r3);
    }
}

// Single-pass exclusive scan with decoupled lookback.
__global__ void scan_onepass() {
    __shared__ int s[TB];
    __shared__ int sbid;
    __shared__ int sprefix;
    int tid = threadIdx.x;
    if (tid == 0) {
        sbid = (int)atomicAdd(&g_zs.ticket, 1u);
        sprefix = 0;
    }
    __syncthreads();
    int bid = sbid;
    int i = bid * TB + tid;
    int v = (i < NNODES) ? g_zs.cnt[i] : 0;
    s[tid] = v;
    __syncthreads();
    #pragma unroll
    for (int off = 1; off < TB; off <<= 1) {
        int x = (tid >= off) ? s[tid - off] : 0;
        __syncthreads();
        s[tid] += x;
        __syncthreads();
    }
    int incl  = s[tid];
    int total = s[TB - 1];

    if (tid == 0) {
        unsigned long long pkt =
            ((unsigned long long)((bid == 0) ? 2u : 1u) << 32) | (unsigned int)total;
        atomicExch(&g_zs.state[bid], pkt);
    }

    if (bid > 0 && tid < 32) {
        int look = bid - 1;
        int pfx = 0;
        for (;;) {
            int j = look - tid;
            int flag, val;
            if (j >= 0) {
                unsigned long long pkt;
                do {
                    pkt = atomicAdd(&g_zs.state[j], 0ULL);
                    flag = (int)(pkt >> 32);
                } while (flag == 0);
                val = (int)(unsigned int)pkt;
            } else { flag = 2; val = 0; }
            unsigned int ball = __ballot_sync(0xffffffffu, flag == 2);
            int first = __ffs(ball) - 1;
            int contrib = (first < 0) ? val : ((tid <= first) ? val : 0);
            #pragma unroll
            for (int o = 16; o; o >>= 1)
                contrib += __shfl_down_sync(0xffffffffu, contrib, o);
            if (tid == 0) pfx += contrib;
            if (ball) break;
            look -= 32;
        }
        if (tid == 0) {
            sprefix = pfx;
            atomicExch(&g_zs.state[bid],
                       ((unsigned long long)2u << 32) | (unsigned int)(total + pfx));
        }
    }
    __syncthreads();
    int excl = sprefix + incl - v;
    if (i < NNODES) g_rowptr[i] = excl;
    if (i == NNODES - 1) g_rowptr[NNODES] = NNZ_E;
}

// Atomic-free scatter (first EDGE4_BLOCKS blocks, 4 edges/thread) fused
// with h0 init (rest).
__global__ void scatter_init_kernel(const int4*   __restrict__ src4,
                                    const int4*   __restrict__ dst4,
                                    const float4* __restrict__ val4,
                                    const float4* __restrict__ user,
                                    const float4* __restrict__ item) {
    if (blockIdx.x < EDGE4_BLOCKS) {
        int t = blockIdx.x * TB + threadIdx.x;
        if (t < NNZ_E / 4) {
            int4   s = __ldg(&src4[t]);
            int4   d = __ldg(&dst4[t]);
            float4 v = __ldg(&val4[t]);
            int4   r = reinterpret_cast<const int4*>(g_rank)[t];
            g_meta[__ldg(&g_rowptr[s.x]) + r.x] = make_int2(d.x, __float_as_int(v.x));
            g_meta[__ldg(&g_rowptr[s.y]) + r.y] = make_int2(d.y, __float_as_int(v.y));
            g_meta[__ldg(&g_rowptr[s.z]) + r.z] = make_int2(d.z, __float_as_int(v.z));
            g_meta[__ldg(&g_rowptr[s.w]) + r.w] = make_int2(d.w, __float_as_int(v.w));
        }
    } else {
        int i = (blockIdx.x - EDGE4_BLOCKS) * TB + threadIdx.x;
        if (i < HVEC) {
            int j = i * 2;
            float4 a = (j     < NUSERS * 16) ? __ldg(&user[j])     : __ldg(&item[j - NUSERS * 16]);
            float4 b = (j + 1 < NUSERS * 16) ? __ldg(&user[j + 1]) : __ldg(&item[j + 1 - NUSERS * 16]);
            union { uint4 u; __half2 h[4]; } o;
            o.h[0] = __floats2half2_rn(a.x, a.y);
            o.h[1] = __floats2half2_rn(a.z, a.w);
            o.h[2] = __floats2half2_rn(b.x, b.y);
            o.h[3] = __floats2half2_rn(b.z, b.w);
            g_h0[i] = o.u;
        }
    }
}

// ---------------- SpMM core: 8 lanes/row, 8 floats/lane ----------------

struct Acc8 { float v[8]; };

__device__ __forceinline__ void fma8(Acc8& a, float w, uint4 u) {
    union { uint4 u; __half2 h[4]; } x;
    x.u = u;
    #pragma unroll
    for (int k = 0; k < 4; k++) {
        float2 f = __half22float2(x.h[k]);
        a.v[2*k]   += w * f.x;
        a.v[2*k+1] += w * f.y;
    }
}

__device__ __forceinline__ Acc8 spmm_row(const uint4* __restrict__ in,
                                         int row, int lane) {
    int beg = __ldg(&g_rowptr[row]);
    int end = __ldg(&g_rowptr[row + 1]);
    Acc8 acc;
    #pragma unroll
    for (int k = 0; k < 8; k++) acc.v[k] = 0.f;
    int i = beg;
    for (; i + 4 <= end; i += 4) {
        int2 m0 = __ldg(&g_meta[i]);
        int2 m1 = __ldg(&g_meta[i + 1]);
        int2 m2 = __ldg(&g_meta[i + 2]);
        int2 m3 = __ldg(&g_meta[i + 3]);
        uint4 x0 = __ldg(&in[m0.x * 8 + lane]);
        uint4 x1 = __ldg(&in[m1.x * 8 + lane]);
        uint4 x2 = __ldg(&in[m2.x * 8 + lane]);
        uint4 x3 = __ldg(&in[m3.x * 8 + lane]);
        fma8(acc, __int_as_float(m0.y), x0);
        fma8(acc, __int_as_float(m1.y), x1);
        fma8(acc, __int_as_float(m2.y), x2);
        fma8(acc, __int_as_float(m3.y), x3);
    }
    for (; i < end; i++) {
        int2 m = __ldg(&g_meta[i]);
        uint4 x = __ldg(&in[m.x * 8 + lane]);
        fma8(acc, __int_as_float(m.y), x);
    }
    return acc;
}

// Layers 1,2: out_h = fp16(A * in)
__global__ void spmm_kernel(const uint4* __restrict__ in,
                            uint4*       __restrict__ out_h) {
    int gtid = blockIdx.x * blockDim.x + threadIdx.x;
    int row  = gtid >> 3;
    int lane = gtid & 7;
    if (row >= NNODES) return;

    Acc8 s = spmm_row(in, row, lane);

    union { uint4 u; __half2 h[4]; } o;
    o.h[0] = __floats2half2_rn(s.v[0], s.v[1]);
    o.h[1] = __floats2half2_rn(s.v[2], s.v[3]);
    o.h[2] = __floats2half2_rn(s.v[4], s.v[5]);
    o.h[3] = __floats2half2_rn(s.v[6], s.v[7]);
    out_h[row * 8 + lane] = o.u;
}

// Layer 3 + epilogue: out = 0.25 * (h0 + h1 + h2 + A*h2)
__global__ void spmm_final_kernel(float4* __restrict__ out) {
    int gtid = blockIdx.x * blockDim.x + threadIdx.x;
    int row  = gtid >> 3;
    int lane = gtid & 7;
    if (row >= NNODES) return;

    Acc8 s = spmm_row(g_h2, row, lane);

    int hidx = row * 8 + lane;
    union { uint4 u; __half2 h[4]; } a, b, c;
    a.u = g_h0[hidx];
    b.u = g_h1[hidx];
    c.u = g_h2[hidx];

    float r[8];
    #pragma unroll
    for (int k = 0; k < 4; k++) {
        float2 fa = __half22float2(a.h[k]);
        float2 fb = __half22float2(b.h[k]);
        float2 fc = __half22float2(c.h[k]);
        r[2*k]   = 0.25f * (fa.x + fb.x + fc.x + s.v[2*k]);
        r[2*k+1] = 0.25f * (fa.y + fb.y + fc.y + s.v[2*k+1]);
    }
    int o0 = row * 16 + lane * 2;
    out[o0]     = make_float4(r[0], r[1], r[2], r[3]);
    out[o0 + 1] = make_float4(r[4], r[5], r[6], r[7]);
}

// ---------------- launch ----------------

extern "C" void kernel_launch(void* const* d_in, const int* in_sizes, int n_in,
                              void* d_out, int out_size) {
    const float4* user = (const float4*)d_in[0];
    const float4* item = (const float4*)d_in[1];
    const int*    esrc = (const int*)d_in[2];
    const int*    edst = (const int*)d_in[3];
    const float*  eval = (const float*)d_in[4];
    float4* out = (float4*)d_out;

    uint4 *h0, *h1, *h2;
    void* zs;
    cudaGetSymbolAddress((void**)&h0, g_h0);
    cudaGetSymbolAddress((void**)&h1, g_h1);
    cudaGetSymbolAddress((void**)&h2, g_h2);
    cudaGetSymbolAddress(&zs, g_zs);

    cudaMemsetAsync(zs, 0, sizeof(ZeroRegion));

    hist_kernel<<<EDGE4_BLOCKS, TB>>>((const int4*)esrc);
    scan_onepass<<<SCAN_NBLK, TB>>>();
    scatter_init_kernel<<<EDGE4_BLOCKS + HVEC_BLOCKS, TB>>>(
        (const int4*)esrc, (const int4*)edst, (const float4*)eval, user, item);

    spmm_kernel<<<HVEC_BLOCKS, TB>>>(h0, h1);
    spmm_kernel<<<HVEC_BLOCKS, TB>>>(h1, h2);
    spmm_final_kernel<<<HVEC_BLOCKS, TB>>>(out);
}

// round 11
// speedup vs baseline: 1.0832x; 1.0832x over previous
#include <cuda_runtime.h>
#include <cuda_fp16.h>
#include <cuda_bf16.h>

// LightGCN: CSR SpMM x3, fp16 feature buffers, fp32 row accumulation.
// Round 11: revert to R6 build (rank detour measured -13us in R10), fix the
// scatter latency chain instead: 4 independent edges/thread (4 parallel
// atomic->store chains, vectorized edge reads). spmm gets
// __launch_bounds__(256,7) to raise occupancy 48->56 warps/SM.

constexpr int NUSERS = 100000;
constexpr int NITEMS = 50000;
constexpr int NNODES = 150000;
constexpr int NNZ_E  = 4800000;
constexpr int HVEC   = NNODES * 8;    // uint4 (8 halves) per fp16 buffer

constexpr int TB           = 256;
constexpr int SCAN_NBLK    = (NNODES + TB - 1) / TB;        // 586
constexpr int EDGE4_BLOCKS = (NNZ_E / 4 + TB - 1) / TB;     // 4688
constexpr int HVEC_BLOCKS  = (HVEC + TB - 1) / TB;          // 4688

// ---- scratch ----
struct ZeroRegion {                    // zeroed with ONE cudaMemsetAsync
    int cnt[NNODES];
    unsigned long long state[SCAN_NBLK];
    unsigned int ticket;
};
__device__ ZeroRegion g_zs;
__device__ uint4 g_h0[HVEC];
__device__ uint4 g_h1[HVEC];
__device__ uint4 g_h2[HVEC];
__device__ int   g_rowptr[NNODES + 1];
__device__ int   g_rowcur[NNODES];
__device__ int2  g_meta[NNZ_E];        // {dst, val bits} grouped by src

// ---------------- CSR build ----------------

// Histogram, 4 edges/thread, fire-and-forget (RED).
__global__ void hist_kernel(const int4* __restrict__ src4) {
    int t = blockIdx.x * blockDim.x + threadIdx.x;
    if (t < NNZ_E / 4) {
        int4 s = __ldg(&src4[t]);
        atomicAdd(&g_zs.cnt[s.x], 1);
        atomicAdd(&g_zs.cnt[s.y], 1);
        atomicAdd(&g_zs.cnt[s.z], 1);
        atomicAdd(&g_zs.cnt[s.w], 1);
    }
}

// Single-pass exclusive scan with decoupled lookback.
__global__ void scan_onepass() {
    __shared__ int s[TB];
    __shared__ int sbid;
    __shared__ int sprefix;
    int tid = threadIdx.x;
    if (tid == 0) {
        sbid = (int)atomicAdd(&g_zs.ticket, 1u);
        sprefix = 0;
    }
    __syncthreads();
    int bid = sbid;
    int i = bid * TB + tid;
    int v = (i < NNODES) ? g_zs.cnt[i] : 0;
    s[tid] = v;
    __syncthreads();
    #pragma unroll
    for (int off = 1; off < TB; off <<= 1) {
        int x = (tid >= off) ? s[tid - off] : 0;
        __syncthreads();
        s[tid] += x;
        __syncthreads();
    }
    int incl  = s[tid];
    int total = s[TB - 1];

    if (tid == 0) {
        unsigned long long pkt =
            ((unsigned long long)((bid == 0) ? 2u : 1u) << 32) | (unsigned int)total;
        atomicExch(&g_zs.state[bid], pkt);
    }

    if (bid > 0 && tid < 32) {
        int look = bid - 1;
        int pfx = 0;
        for (;;) {
            int j = look - tid;
            int flag, val;
            if (j >= 0) {
                unsigned long long pkt;
                do {
                    pkt = atomicAdd(&g_zs.state[j], 0ULL);
                    flag = (int)(pkt >> 32);
                } while (flag == 0);
                val = (int)(unsigned int)pkt;
            } else { flag = 2; val = 0; }
            unsigned int ball = __ballot_sync(0xffffffffu, flag == 2);
            int first = __ffs(ball) - 1;
            int contrib = (first < 0) ? val : ((tid <= first) ? val : 0);
            #pragma unroll
            for (int o = 16; o; o >>= 1)
                contrib += __shfl_down_sync(0xffffffffu, contrib, o);
            if (tid == 0) pfx += contrib;
            if (ball) break;
            look -= 32;
        }
        if (tid == 0) {
            sprefix = pfx;
            atomicExch(&g_zs.state[bid],
                       ((unsigned long long)2u << 32) | (unsigned int)(total + pfx));
        }
    }
    __syncthreads();
    int excl = sprefix + incl - v;
    if (i < NNODES) {
        g_rowptr[i] = excl;
        g_rowcur[i] = excl;
    }
    if (i == NNODES - 1) g_rowptr[NNODES] = NNZ_E;
}

// Scatter (first EDGE4_BLOCKS blocks, 4 independent edges/thread) fused
// with h0 init (rest).
__global__ void scatter_init_kernel(const int4*   __restrict__ src4,
                                    const int4*   __restrict__ dst4,
                                    const float4* __restrict__ val4,
                                    const float4* __restrict__ user,
                                    const float4* __restrict__ item) {
    if (blockIdx.x < EDGE4_BLOCKS) {
        int t = blockIdx.x * TB + threadIdx.x;
        if (t < NNZ_E / 4) {
            int4   s = __ldg(&src4[t]);
            int4   d = __ldg(&dst4[t]);
            float4 v = __ldg(&val4[t]);
            // 4 independent atomic->store chains per thread (MLP=4)
            int p0 = atomicAdd(&g_rowcur[s.x], 1);
            int p1 = atomicAdd(&g_rowcur[s.y], 1);
            int p2 = atomicAdd(&g_rowcur[s.z], 1);
            int p3 = atomicAdd(&g_rowcur[s.w], 1);
            g_meta[p0] = make_int2(d.x, __float_as_int(v.x));
            g_meta[p1] = make_int2(d.y, __float_as_int(v.y));
            g_meta[p2] = make_int2(d.z, __float_as_int(v.z));
            g_meta[p3] = make_int2(d.w, __float_as_int(v.w));
        }
    } else {
        int i = (blockIdx.x - EDGE4_BLOCKS) * TB + threadIdx.x;
        if (i < HVEC) {
            int j = i * 2;
            float4 a = (j     < NUSERS * 16) ? __ldg(&user[j])     : __ldg(&item[j - NUSERS * 16]);
            float4 b = (j + 1 < NUSERS * 16) ? __ldg(&user[j + 1]) : __ldg(&item[j + 1 - NUSERS * 16]);
            union { uint4 u; __half2 h[4]; } o;
            o.h[0] = __floats2half2_rn(a.x, a.y);
            o.h[1] = __floats2half2_rn(a.z, a.w);
            o.h[2] = __floats2half2_rn(b.x, b.y);
            o.h[3] = __floats2half2_rn(b.z, b.w);
            g_h0[i] = o.u;
        }
    }
}

// ---------------- SpMM core: 8 lanes/row, 8 floats/lane ----------------

struct Acc8 { float v[8]; };

__device__ __forceinline__ void fma8(Acc8& a, float w, uint4 u) {
    union { uint4 u; __half2 h[4]; } x;
    x.u = u;
    #pragma unroll
    for (int k = 0; k < 4; k++) {
        float2 f = __half22float2(x.h[k]);
        a.v[2*k]   += w * f.x;
        a.v[2*k+1] += w * f.y;
    }
}

__device__ __forceinline__ Acc8 spmm_row(const uint4* __restrict__ in,
                                         int row, int lane) {
    int beg = __ldg(&g_rowptr[row]);
    int end = __ldg(&g_rowptr[row + 1]);
    Acc8 acc;
    #pragma unroll
    for (int k = 0; k < 8; k++) acc.v[k] = 0.f;
    int i = beg;
    for (; i + 4 <= end; i += 4) {
        int2 m0 = __ldg(&g_meta[i]);
        int2 m1 = __ldg(&g_meta[i + 1]);
        int2 m2 = __ldg(&g_meta[i + 2]);
        int2 m3 = __ldg(&g_meta[i + 3]);
        uint4 x0 = __ldg(&in[m0.x * 8 + lane]);
        uint4 x1 = __ldg(&in[m1.x * 8 + lane]);
        uint4 x2 = __ldg(&in[m2.x * 8 + lane]);
        uint4 x3 = __ldg(&in[m3.x * 8 + lane]);
        fma8(acc, __int_as_float(m0.y), x0);
        fma8(acc, __int_as_float(m1.y), x1);
        fma8(acc, __int_as_float(m2.y), x2);
        fma8(acc, __int_as_float(m3.y), x3);
    }
    for (; i < end; i++) {
        int2 m = __ldg(&g_meta[i]);
        uint4 x = __ldg(&in[m.x * 8 + lane]);
        fma8(acc, __int_as_float(m.y), x);
    }
    return acc;
}

// Layers 1,2: out_h = fp16(A * in)
__global__ void __launch_bounds__(256, 7)
spmm_kernel(const uint4* __restrict__ in,
            uint4*       __restrict__ out_h) {
    int gtid = blockIdx.x * blockDim.x + threadIdx.x;
    int row  = gtid >> 3;
    int lane = gtid & 7;
    if (row >= NNODES) return;

    Acc8 s = spmm_row(in, row, lane);

    union { uint4 u; __half2 h[4]; } o;
    o.h[0] = __floats2half2_rn(s.v[0], s.v[1]);
    o.h[1] = __floats2half2_rn(s.v[2], s.v[3]);
    o.h[2] = __floats2half2_rn(s.v[4], s.v[5]);
    o.h[3] = __floats2half2_rn(s.v[6], s.v[7]);
    out_h[row * 8 + lane] = o.u;
}

// Layer 3 + epilogue: out = 0.25 * (h0 + h1 + h2 + A*h2)
__global__ void __launch_bounds__(256, 7)
spmm_final_kernel(float4* __restrict__ out) {
    int gtid = blockIdx.x * blockDim.x + threadIdx.x;
    int row  = gtid >> 3;
    int lane = gtid & 7;
    if (row >= NNODES) return;

    Acc8 s = spmm_row(g_h2, row, lane);

    int hidx = row * 8 + lane;
    union { uint4 u; __half2 h[4]; } a, b, c;
    a.u = g_h0[hidx];
    b.u = g_h1[hidx];
    c.u = g_h2[hidx];

    float r[8];
    #pragma unroll
    for (int k = 0; k < 4; k++) {
        float2 fa = __half22float2(a.h[k]);
        float2 fb = __half22float2(b.h[k]);
        float2 fc = __half22float2(c.h[k]);
        r[2*k]   = 0.25f * (fa.x + fb.x + fc.x + s.v[2*k]);
        r[2*k+1] = 0.25f * (fa.y + fb.y + fc.y + s.v[2*k+1]);
    }
    int o0 = row * 16 + lane * 2;
    out[o0]     = make_float4(r[0], r[1], r[2], r[3]);
    out[o0 + 1] = make_float4(r[4], r[5], r[6], r[7]);
}

// ---------------- launch ----------------

extern "C" void kernel_launch(void* const* d_in, const int* in_sizes, int n_in,
                              void* d_out, int out_size) {
    const float4* user = (const float4*)d_in[0];
    const float4* item = (const float4*)d_in[1];
    const int*    esrc = (const int*)d_in[2];
    const int*    edst = (const int*)d_in[3];
    const float*  eval = (const float*)d_in[4];
    float4* out = (float4*)d_out;

    uint4 *h0, *h1, *h2;
    void* zs;
    cudaGetSymbolAddress((void**)&h0, g_h0);
    cudaGetSymbolAddress((void**)&h1, g_h1);
    cudaGetSymbolAddress((void**)&h2, g_h2);
    cudaGetSymbolAddress(&zs, g_zs);

    cudaMemsetAsync(zs, 0, sizeof(ZeroRegion));

    hist_kernel<<<EDGE4_BLOCKS, TB>>>((const int4*)esrc);
    scan_onepass<<<SCAN_NBLK, TB>>>();
    scatter_init_kernel<<<EDGE4_BLOCKS + HVEC_BLOCKS, TB>>>(
        (const int4*)esrc, (const int4*)edst, (const float4*)eval, user, item);

    spmm_kernel<<<HVEC_BLOCKS, TB>>>(h0, h1);
    spmm_kernel<<<HVEC_BLOCKS, TB>>>(h1, h2);
    spmm_final_kernel<<<HVEC_BLOCKS, TB>>>(out);
}